// round 13
// baseline (speedup 1.0000x reference)
#include <cuda_runtime.h>

// GaussianBlur2D: depthwise 11x11 Gaussian blur, reflect padding.
// x: (16, 64, 512, 512) fp32, sigma: (1,) fp32.
//
// Horizontal-first, ZERO smem / ZERO barriers (warp-autonomous):
//   - 14-deep register window of H-BLURRED rows; vertical 11-tap -> STG.128
//   - per row: own quad q (prefetched early, DRAM), L/R neighbor quads
//     fetched inline (L1 hits - same lines as neighbors' q), end taps
//     x-5/x+8 via 2 shuffles from q; edge lanes patch via reflect loads
//   - sigma==1.5 fast path: fma.rn.f32 immediate weights (no weight regs);
//     generic runtime-sigma path otherwise
// g2d[i][j] = (h[i]/S)*(h[j]/S) with S = sum(h)  == reference's 2D kernel.

#define KS    11
#define IMG   512
#define NT    128      // threads per block; NT*4 == IMG
#define RPT   4        // output rows per iteration
#define STRIP 128      // output rows per block
#define FULL  0xffffffffu

// fma.rn.f32 acc = v * <imm> + acc   (imm as PTX hex float literal)
#define FMA_IMM(acc, v, HEX) \
    asm("fma.rn.f32 %0, %1, " HEX ", %0;" : "+f"(acc) : "f"(v))

// Normalized 1D Gaussian weights for sigma=1.5 (IEEE-754 fp32 hex)
#define W_0  "0f3A86CAB4"
#define W_1  "0f3BF8FF33"
#define W_2  "0f3D137578"
#define W_3  "0f3DDFF8A9"
#define W_4  "0f3E5A1E3F"
#define W_5  "0f3E8832BD"
#define W_6  W_4
#define W_7  W_3
#define W_8  W_2
#define W_9  W_1
#define W_10 W_0

// horizontal tap j over v[]
#define HT(j, HEX) {                                                \
    FMA_IMM(o0, v[(j)],     HEX); FMA_IMM(o1, v[(j) + 1], HEX);     \
    FMA_IMM(o2, v[(j) + 2], HEX); FMA_IMM(o3, v[(j) + 3], HEX); }

// vertical tap i over win[r+i]
#define VT(i, HEX) { const float4 v_ = win[r + (i)];                \
    FMA_IMM(a0, v_.x, HEX); FMA_IMM(a1, v_.y, HEX);                 \
    FMA_IMM(a2, v_.z, HEX); FMA_IMM(a3, v_.w, HEX); }

__device__ __forceinline__ int refl(int i) {
    i = (i < 0) ? -i : i;
    return (i >= IMG) ? (2 * IMG - 2 - i) : i;
}

// Horizontal 11-tap for cols x..x+3 of one row, own quad q already loaded.
// L/R quads come from memory (L1 hits); end taps via lane+-2 shuffles.
template<bool SPEC>
__device__ __forceinline__ float4 hblur_q(float4 q, const float* __restrict__ row,
                                          int x, int t, int lane,
                                          const float* __restrict__ w) {
    float4 L, R;
    if (t != 0)      L = *(const float4*)(row + x - 4);
    else             L = make_float4(row[4],   row[3],   row[2],   row[1]);
    if (t != NT - 1) R = *(const float4*)(row + x + 4);
    else             R = make_float4(row[510], row[509], row[508], row[507]);

    float v0  = __shfl_up_sync  (FULL, q.w, 2);   // col x-5 (lane-2's q.w)
    float v13 = __shfl_down_sync(FULL, q.x, 2);   // col x+8 (lane+2's q.x)
    if (lane < 2)   v0  = row[refl(x - 5)];
    if (lane >= 30) v13 = row[refl(x + 8)];

    const float v[14] = {v0, L.x, L.y, L.z, L.w,
                         q.x, q.y, q.z, q.w,
                         R.x, R.y, R.z, R.w, v13};
    float o0 = 0.f, o1 = 0.f, o2 = 0.f, o3 = 0.f;
    if constexpr (SPEC) {
        HT(0, W_0)  HT(1, W_1)  HT(2, W_2)  HT(3, W_3)
        HT(4, W_4)  HT(5, W_5)  HT(6, W_6)  HT(7, W_7)
        HT(8, W_8)  HT(9, W_9)  HT(10, W_10)
    } else {
        #pragma unroll
        for (int j = 0; j < KS; j++) {
            const float wj = w[j];
            o0 = fmaf(wj, v[j],     o0);
            o1 = fmaf(wj, v[j + 1], o1);
            o2 = fmaf(wj, v[j + 2], o2);
            o3 = fmaf(wj, v[j + 3], o3);
        }
    }
    return make_float4(o0, o1, o2, o3);
}

template<bool SPEC>
__device__ __forceinline__ void blur_body(const float* __restrict__ img,
                                          float* __restrict__ oimg,
                                          int t, int y0, float sig) {
    const int lane = t & 31;
    const int x    = t << 2;               // this thread owns columns x..x+3

    float w[KS];
    if constexpr (!SPEC) {
        float s = fabsf(sig) + 1e-6f;
        float inv = 1.0f / (2.0f * s * s);
        float sum = 0.0f;
        #pragma unroll
        for (int j = 0; j < KS; j++) {
            float r = (float)j - (float)(KS - 1) * 0.5f;
            w[j] = __expf(-r * r * inv);
            sum += w[j];
        }
        float rs = 1.0f / sum;
        #pragma unroll
        for (int j = 0; j < KS; j++) w[j] *= rs;
    }

    // win[k] = hblur of input row (y0 + k - 5), k = 0..13
    float4 win[14];
    #pragma unroll
    for (int k = 0; k < 14; k++) {
        const float* row = img + (size_t)refl(y0 + k - 5) * IMG;
        win[k] = hblur_q<SPEC>(*(const float4*)(row + x), row, x, t, lane, w);
    }

    for (int yb = 0; yb < STRIP; yb += RPT) {
        const int y = y0 + yb;

        // Prefetch the own quads of rows y+9..y+12 (the DRAM-missing lines),
        // 4-deep MLP issued before the vertical FMA stream.
        int   roff[RPT];
        float4 nq[RPT];
        #pragma unroll
        for (int rr = 0; rr < RPT; rr++) {
            roff[rr] = refl(y + 9 + rr) * IMG;
            nq[rr]   = *(const float4*)(img + (size_t)roff[rr] + x);
        }

        // ---- vertical 11-tap over h-blurred window -> outputs ----
        #pragma unroll
        for (int r = 0; r < RPT; r++) {
            float a0 = 0.f, a1 = 0.f, a2 = 0.f, a3 = 0.f;
            if constexpr (SPEC) {
                VT(0, W_0)  VT(1, W_1)  VT(2, W_2)  VT(3, W_3)
                VT(4, W_4)  VT(5, W_5)  VT(6, W_6)  VT(7, W_7)
                VT(8, W_8)  VT(9, W_9)  VT(10, W_10)
            } else {
                #pragma unroll
                for (int i = 0; i < KS; i++) {
                    const float  wi = w[i];
                    const float4 v  = win[r + i];
                    a0 = fmaf(wi, v.x, a0);
                    a1 = fmaf(wi, v.y, a1);
                    a2 = fmaf(wi, v.z, a2);
                    a3 = fmaf(wi, v.w, a3);
                }
            }
            *(float4*)(oimg + (size_t)(y + r) * IMG + x) = make_float4(a0, a1, a2, a3);
        }

        // ---- h-blur the arrived rows; slide window down by RPT ----
        float4 hb[RPT];
        #pragma unroll
        for (int rr = 0; rr < RPT; rr++)
            hb[rr] = hblur_q<SPEC>(nq[rr], img + (size_t)roff[rr], x, t, lane, w);

        #pragma unroll
        for (int k = 0; k < 14 - RPT; k++) win[k] = win[k + RPT];
        #pragma unroll
        for (int rr = 0; rr < RPT; rr++)   win[10 + rr] = hb[rr];
    }
}

__global__ __launch_bounds__(NT, 5)
void gaussian_blur_kernel(const float* __restrict__ in, float* __restrict__ out,
                          const float* __restrict__ sigma) {
    const int t = threadIdx.x;
    const int plane = blockIdx.x >> 2;
    const int y0 = (blockIdx.x & 3) * STRIP;
    const float* __restrict__ img  = in  + (size_t)plane * (IMG * IMG);
    float*       __restrict__ oimg = out + (size_t)plane * (IMG * IMG);

    const float sig = sigma[0];
    if (fabsf(fabsf(sig) - 1.5f) < 1e-4f) {
        blur_body<true >(img, oimg, t, y0, sig);
    } else {
        blur_body<false>(img, oimg, t, y0, sig);
    }
}

extern "C" void kernel_launch(void* const* d_in, const int* in_sizes, int n_in,
                              void* d_out, int out_size) {
    const float* x     = (const float*)d_in[0];
    const float* sigma = (const float*)d_in[1];
    float*       out   = (float*)d_out;

    const int n_img = in_sizes[0] / (IMG * IMG);   // B*C planes

    const int strips = IMG / STRIP;                // 4
    gaussian_blur_kernel<<<n_img * strips, NT>>>(x, out, sigma);
}